// round 2
// baseline (speedup 1.0000x reference)
#include <cuda_runtime.h>
#include <math.h>

#define Bx 512
#define Tx 256
#define Ix 256
#define Hx 512
#define G4 2048   // 4*Hx

// Scratch (allocation-free rule: __device__ globals)
__device__ float g_xg[(size_t)Tx * Bx * G4];   // [t][b][4H]  (1 GB)
__device__ float g_hs[(size_t)Tx * Bx * Hx];   // [t][b][H]   (256 MB)
__device__ float g_h0[Bx * Hx];
__device__ float g_c [Bx * Hx];

// ---- packed f32x2 helpers (FFMA2: 2 scalar FMAs per issue; ptxas never
// emits this from C++, only via PTX fma.rn.f32x2) ----------------------------
__device__ __forceinline__ unsigned long long pack2(float a, float b) {
    unsigned long long r;
    asm("mov.b64 %0, {%1, %2};" : "=l"(r) : "f"(a), "f"(b));
    return r;
}
__device__ __forceinline__ void unpack2(unsigned long long v, float& a, float& b) {
    asm("mov.b64 {%0, %1}, %2;" : "=f"(a), "=f"(b) : "l"(v));
}
__device__ __forceinline__ void ffma2(unsigned long long& d,
                                      unsigned long long a,
                                      unsigned long long b) {
    asm("fma.rn.f32x2 %0, %1, %2, %0;" : "+l"(d) : "l"(a), "l"(b));
}

// ---------------------------------------------------------------------------
__global__ void init_kernel() {
    int i = blockIdx.x * blockDim.x + threadIdx.x;
    if (i < Bx * Hx) { g_h0[i] = 0.f; g_c[i] = 0.f; }
}

// ---------------------------------------------------------------------------
// xg[t][b][j] = sum_i x[b][t][i] * Wih[j][i] + bih[j] + bhh[j]
// Block tile: 64 b x 64 j, K = 256 in chunks of 16. 256 threads, 4x4 per thread.
__global__ __launch_bounds__(256) void pregemm_kernel(
    const float* __restrict__ x, const float* __restrict__ Wih,
    const float* __restrict__ bih, const float* __restrict__ bhh)
{
    __shared__ float sx[16][68];   // [k][b]   row = 272 B (16-aligned)
    __shared__ float sw[16][68];   // [k][j]
    const int tid = threadIdx.x;
    const int tx = tid & 15, ty = tid >> 4;
    const int j0 = blockIdx.x * 64, b0 = blockIdx.y * 64, t = blockIdx.z;

    // acc[i][0] packs j-pair (0,1); acc[i][1] packs j-pair (2,3)
    unsigned long long acc[4][2];
    #pragma unroll
    for (int i = 0; i < 4; i++) { acc[i][0] = 0ULL; acc[i][1] = 0ULL; }

    const int r = tid >> 2;            // 0..63
    const int q = (tid & 3) * 4;       // 0,4,8,12
    const float* xrow = x + ((size_t)(b0 + r) * Tx + t) * Ix;
    const float* wrow = Wih + (size_t)(j0 + r) * Ix;

    for (int k0 = 0; k0 < Ix; k0 += 16) {
        float4 xv = *(const float4*)(xrow + k0 + q);
        float4 wv = *(const float4*)(wrow + k0 + q);
        sx[q + 0][r] = xv.x; sx[q + 1][r] = xv.y; sx[q + 2][r] = xv.z; sx[q + 3][r] = xv.w;
        sw[q + 0][r] = wv.x; sw[q + 1][r] = wv.y; sw[q + 2][r] = wv.z; sw[q + 3][r] = wv.w;
        __syncthreads();
        #pragma unroll
        for (int k = 0; k < 16; k++) {
            float4 xf = *(float4*)&sx[k][ty * 4];
            unsigned long long wA = *(const unsigned long long*)&sw[k][tx * 4];
            unsigned long long wB = *(const unsigned long long*)&sw[k][tx * 4 + 2];
            unsigned long long hh[4];
            hh[0] = pack2(xf.x, xf.x); hh[1] = pack2(xf.y, xf.y);
            hh[2] = pack2(xf.z, xf.z); hh[3] = pack2(xf.w, xf.w);
            #pragma unroll
            for (int i = 0; i < 4; i++) {
                ffma2(acc[i][0], hh[i], wA);
                ffma2(acc[i][1], hh[i], wB);
            }
        }
        __syncthreads();
    }

    float bs[4];
    #pragma unroll
    for (int j = 0; j < 4; j++) {
        int jj = j0 + tx * 4 + j;
        bs[j] = bih[jj] + bhh[jj];
    }
    #pragma unroll
    for (int i = 0; i < 4; i++) {
        int b = b0 + ty * 4 + i;
        float a0, a1, a2, a3;
        unpack2(acc[i][0], a0, a1);
        unpack2(acc[i][1], a2, a3);
        float4 o;
        o.x = a0 + bs[0]; o.y = a1 + bs[1];
        o.z = a2 + bs[2]; o.w = a3 + bs[3];
        *(float4*)&g_xg[((size_t)t * Bx + b) * G4 + j0 + tx * 4] = o;
    }
}

// ---------------------------------------------------------------------------
// One scan step: G = xg_t + h_prev @ Whh^T, then LSTM cell.
// Block computes a [64 b x 32 h'] tile across ALL 4 gates so the cell is
// thread-local. Grid (16, 8) = 128 blocks. 256 threads; per thread 4b x 2j x 4g.
__global__ __launch_bounds__(256) void step_kernel(const float* __restrict__ Whh, int t)
{
    __shared__ float sh[32][68];    // [k][b]            row = 272 B
    __shared__ float sw[32][130];   // [k][gate*32+jj]   row = 520 B (8-aligned)
    const int tid = threadIdx.x;
    const int tx = tid & 15, ty = tid >> 4;
    const int j0 = blockIdx.x * 32, b0 = blockIdx.y * 64;

    const float* hprev = (t == 0) ? g_h0 : (g_hs + (size_t)(t - 1) * Bx * Hx);
    const float* xgt   = g_xg + (size_t)t * Bx * G4;
    float* hout        = g_hs + (size_t)t * Bx * Hx;

    // acc[g][i] packs the (p=0, p=1) j-pair
    unsigned long long acc[4][4];
    #pragma unroll
    for (int g = 0; g < 4; g++)
        #pragma unroll
        for (int i = 0; i < 4; i++) acc[g][i] = 0ULL;

    const int rh = tid >> 2;          // 0..63  (b row)
    const int qh = (tid & 3) * 4;     // 0,4,8,12

    for (int k0 = 0; k0 < Hx; k0 += 32) {
        // h tile (transposed)
        {
            const float* hp = hprev + (size_t)(b0 + rh) * Hx + k0;
            float4 v0 = *(const float4*)(hp + qh);
            float4 v1 = *(const float4*)(hp + 16 + qh);
            sh[qh + 0][rh] = v0.x; sh[qh + 1][rh] = v0.y; sh[qh + 2][rh] = v0.z; sh[qh + 3][rh] = v0.w;
            sh[16 + qh + 0][rh] = v1.x; sh[16 + qh + 1][rh] = v1.y; sh[16 + qh + 2][rh] = v1.z; sh[16 + qh + 3][rh] = v1.w;
        }
        // Whh tile (transposed), 128 rows = 4 gates x 32 jj
        #pragma unroll
        for (int it = 0; it < 4; it++) {
            int lin = tid + it * 256;
            int rw = lin >> 3;              // 0..127
            int qw = (lin & 7) * 4;         // 0..28
            int gate = rw >> 5, jj = rw & 31;
            float4 v = *(const float4*)(Whh + (size_t)(gate * Hx + j0 + jj) * Hx + k0 + qw);
            sw[qw + 0][rw] = v.x; sw[qw + 1][rw] = v.y; sw[qw + 2][rw] = v.z; sw[qw + 3][rw] = v.w;
        }
        __syncthreads();
        #pragma unroll
        for (int k = 0; k < 32; k++) {
            float4 hf = *(float4*)&sh[k][ty * 4];
            unsigned long long hh[4];
            hh[0] = pack2(hf.x, hf.x); hh[1] = pack2(hf.y, hf.y);
            hh[2] = pack2(hf.z, hf.z); hh[3] = pack2(hf.w, hf.w);
            unsigned long long w0 = *(const unsigned long long*)&sw[k][  0 + tx * 2];
            unsigned long long w1 = *(const unsigned long long*)&sw[k][ 32 + tx * 2];
            unsigned long long w2 = *(const unsigned long long*)&sw[k][ 64 + tx * 2];
            unsigned long long w3 = *(const unsigned long long*)&sw[k][ 96 + tx * 2];
            #pragma unroll
            for (int i = 0; i < 4; i++) {
                ffma2(acc[0][i], hh[i], w0);
                ffma2(acc[1][i], hh[i], w1);
                ffma2(acc[2][i], hh[i], w2);
                ffma2(acc[3][i], hh[i], w3);
            }
        }
        __syncthreads();
    }

    // LSTM cell epilogue (thread owns all 4 gates for each of its (b, j))
    #pragma unroll
    for (int i = 0; i < 4; i++) {
        int b = b0 + ty * 4 + i;
        const float* xb = xgt + (size_t)b * G4;
        float gi[2], gf[2], gg[2], go[2];
        unpack2(acc[0][i], gi[0], gi[1]);
        unpack2(acc[1][i], gf[0], gf[1]);
        unpack2(acc[2][i], gg[0], gg[1]);
        unpack2(acc[3][i], go[0], go[1]);
        #pragma unroll
        for (int p = 0; p < 2; p++) {
            int j = j0 + tx * 2 + p;
            float vi = gi[p] + xb[j];
            float vf = gf[p] + xb[Hx + j];
            float vg = gg[p] + xb[2 * Hx + j];
            float vo = go[p] + xb[3 * Hx + j];
            float si = 1.f / (1.f + expf(-vi));
            float sf = 1.f / (1.f + expf(-vf));
            float tg = tanhf(vg);
            float so = 1.f / (1.f + expf(-vo));
            float cold = g_c[b * Hx + j];
            float cn = sf * cold + si * tg;
            g_c[b * Hx + j] = cn;
            hout[b * Hx + j] = so * tanhf(cn);
        }
    }
}

// ---------------------------------------------------------------------------
// Per-t fused epilogue: fc1 -> BN1(train, biased var, channels=t) -> leaky(0.1)
// -> fc2 -> BN2 -> relu. One block per t, 512 threads (thread = b).
__device__ __forceinline__ void block_reduce2(float& a, float& b, float* ba, float* bb) {
    const unsigned m = 0xffffffffu;
    #pragma unroll
    for (int o = 16; o; o >>= 1) { a += __shfl_xor_sync(m, a, o); b += __shfl_xor_sync(m, b, o); }
    int lane = threadIdx.x & 31, wid = threadIdx.x >> 5;
    if (lane == 0) { ba[wid] = a; bb[wid] = b; }
    __syncthreads();
    if (wid == 0) {
        a = (lane < 16) ? ba[lane] : 0.f;
        b = (lane < 16) ? bb[lane] : 0.f;
        #pragma unroll
        for (int o = 8; o; o >>= 1) { a += __shfl_xor_sync(m, a, o); b += __shfl_xor_sync(m, b, o); }
        if (lane == 0) { ba[0] = a; bb[0] = b; }
    }
    __syncthreads();
    a = ba[0]; b = bb[0];
}

__global__ __launch_bounds__(512) void final_kernel(
    const float* __restrict__ fc1_w, const float* __restrict__ fc1_b,
    const float* __restrict__ fc2_w, const float* __restrict__ fc2_b,
    const float* __restrict__ bn1_g, const float* __restrict__ bn1_b,
    const float* __restrict__ bn2_g, const float* __restrict__ bn2_b,
    float* __restrict__ out)
{
    __shared__ float sW[128][32];   // fc1_w^T chunk: [h][o]
    __shared__ float ra[16], rb[16];
    const int t = blockIdx.x, b = threadIdx.x;

    float a[32];
    #pragma unroll
    for (int o = 0; o < 32; o++) a[o] = 0.f;

    for (int h0 = 0; h0 < Hx; h0 += 128) {
        __syncthreads();
        for (int idx = b; idx < 128 * 32; idx += 512) {
            int h = idx >> 5, o = idx & 31;
            sW[h][o] = fc1_w[(size_t)o * Hx + h0 + h];
        }
        __syncthreads();
        const float* hrow = g_hs + (size_t)t * Bx * Hx + (size_t)b * Hx + h0;
        for (int h = 0; h < 128; h += 4) {
            float4 hv = *(const float4*)(hrow + h);
            float hva[4] = {hv.x, hv.y, hv.z, hv.w};
            #pragma unroll
            for (int m = 0; m < 4; m++)
                #pragma unroll
                for (int o = 0; o < 32; o++) a[o] += hva[m] * sW[h + m][o];
        }
    }

    float s = 0.f, ss = 0.f;
    #pragma unroll
    for (int o = 0; o < 32; o++) {
        a[o] += fc1_b[o];
        s += a[o]; ss += a[o] * a[o];
    }
    block_reduce2(s, ss, ra, rb);
    const float invN1 = 1.f / (512.f * 32.f);
    float m1 = s * invN1;
    float v1 = ss * invN1 - m1 * m1;
    float sc1 = rsqrtf(v1 + 1e-5f) * bn1_g[t];
    float sh1 = bn1_b[t];

    float z = fc2_b[0];
    #pragma unroll
    for (int o = 0; o < 32; o++) {
        float an = (a[o] - m1) * sc1 + sh1;
        an = (an < 0.f) ? 0.1f * an : an;
        z += an * fc2_w[o];
    }

    float zs = z, zss = z * z;
    block_reduce2(zs, zss, ra, rb);
    float m2 = zs * (1.f / 512.f);
    float v2 = zss * (1.f / 512.f) - m2 * m2;
    float zn = (z - m2) * rsqrtf(v2 + 1e-5f) * bn2_g[t] + bn2_b[t];
    out[(size_t)b * Tx + t] = fmaxf(zn, 0.f);
}

// ---------------------------------------------------------------------------
extern "C" void kernel_launch(void* const* d_in, const int* in_sizes, int n_in,
                              void* d_out, int out_size)
{
    const float* x     = (const float*)d_in[0];
    const float* Wih   = (const float*)d_in[1];
    const float* Whh   = (const float*)d_in[2];
    const float* bih   = (const float*)d_in[3];
    const float* bhh   = (const float*)d_in[4];
    const float* fc1_w = (const float*)d_in[5];
    const float* fc1_b = (const float*)d_in[6];
    const float* fc2_w = (const float*)d_in[7];
    const float* fc2_b = (const float*)d_in[8];
    const float* bn1_g = (const float*)d_in[9];
    const float* bn1_b = (const float*)d_in[10];
    const float* bn2_g = (const float*)d_in[11];
    const float* bn2_b = (const float*)d_in[12];
    float* out = (float*)d_out;

    init_kernel<<<(Bx * Hx + 255) / 256, 256>>>();

    pregemm_kernel<<<dim3(G4 / 64, Bx / 64, Tx), 256>>>(x, Wih, bih, bhh);

    for (int t = 0; t < Tx; t++)
        step_kernel<<<dim3(Hx / 32, Bx / 64), 256>>>(Whh, t);

    final_kernel<<<Tx, 512>>>(fc1_w, fc1_b, fc2_w, fc2_b,
                              bn1_g, bn1_b, bn2_g, bn2_b, out);
}